// round 4
// baseline (speedup 1.0000x reference)
#include <cuda_runtime.h>
#include <cstdint>

#define S_DIM 51
#define B_DIM 2048
#define H_DIM 1024
#define OUT_DIM 904
#define M_DIM (S_DIM * B_DIM)   /* 104448 */
#define NARG (M_DIM * 6)        /* 626688 */
#define NEG_BIG (-1.0e30f)
#define MARGIN 2.5e-3f          /* > gumbel span (20.41) * 1e-4 */

// scratch for fc output [M_DIM, OUT_DIM] (377.8 MB)
__device__ float g_fc[(size_t)M_DIM * OUT_DIM];

// ---------------- Threefry-2x32 (20 rounds) ----------------
__device__ __forceinline__ uint2 tf2x32(uint32_t k0, uint32_t k1,
                                        uint32_t c0, uint32_t c1) {
    uint32_t ks2 = k0 ^ k1 ^ 0x1BD11BDAu;
    uint32_t x0 = c0 + k0, x1 = c1 + k1;
    uint32_t ks[3] = {k0, k1, ks2};
    const int RA[4] = {13, 15, 26, 6};
    const int RB[4] = {17, 29, 16, 24};
#pragma unroll
    for (int blk = 0; blk < 5; blk++) {
        const int* rr = (blk & 1) ? RB : RA;
#pragma unroll
        for (int i = 0; i < 4; i++) {
            x0 += x1; x1 = __funnelshift_l(x1, x1, rr[i]); x1 ^= x0;
        }
        x0 += ks[(blk + 1) % 3];
        x1 += ks[(blk + 2) % 3] + (uint32_t)(blk + 1);
    }
    return make_uint2(x0, x1);
}

// partitionable random_bits: fold both lanes of threefry(key, (0, idx))
__device__ __forceinline__ uint32_t rand32(uint32_t k0, uint32_t k1, uint32_t idx) {
    uint2 r = tf2x32(k0, k1, 0u, idx);
    return r.x ^ r.y;
}

__device__ __forceinline__ float gumbel_u32(uint32_t bits) {
    float f = __uint_as_float((bits >> 9) | 0x3f800000u) - 1.0f;
    float u = fmaxf(f, 1.17549435e-38f);
    return -logf(-logf(u));
}

__device__ __forceinline__ float normal_u32(uint32_t bits) {
    float f = __uint_as_float((bits >> 9) | 0x3f800000u) - 1.0f;
    const float lo = -0.99999994f;
    float u = fmaxf(f * 2.0f + lo, lo);
    return 1.41421356237f * erfinvf(u);
}

// ---------------- GEMM: g_fc = A[M,1024] * W[904,1024]^T + b ----------------
#define BM 128
#define BN 64
#define BK 16

__global__ __launch_bounds__(256)
void gemm_kernel(const float* __restrict__ A, const float* __restrict__ W,
                 const float* __restrict__ bias) {
    __shared__ float As[BK][BM + 4];
    __shared__ float Bs[BK][BN + 4];

    const int tid = threadIdx.x;
    const int tx = tid & 15;
    const int ty = tid >> 4;
    const int row0 = blockIdx.y * BM;
    const int col0 = blockIdx.x * BN;

    float acc[8][4];
#pragma unroll
    for (int i = 0; i < 8; i++)
#pragma unroll
        for (int j = 0; j < 4; j++) acc[i][j] = 0.0f;

    const int ar0 = tid >> 2, ar1 = ar0 + 64;
    const int ak = (tid & 3) << 2;
    const int br = tid >> 2;
    const int bk = (tid & 3) << 2;
    const bool bvalid = (col0 + br) < OUT_DIM;

    const float* Ap0 = A + (size_t)(row0 + ar0) * H_DIM + ak;
    const float* Ap1 = A + (size_t)(row0 + ar1) * H_DIM + ak;
    const float* Wp  = W + (size_t)(col0 + br) * H_DIM + bk;

    float4 pa0 = *(const float4*)Ap0;
    float4 pa1 = *(const float4*)Ap1;
    float4 pb = bvalid ? *(const float4*)Wp : make_float4(0.f, 0.f, 0.f, 0.f);

    for (int k0 = 0; k0 < H_DIM; k0 += BK) {
        As[ak + 0][ar0] = pa0.x; As[ak + 1][ar0] = pa0.y;
        As[ak + 2][ar0] = pa0.z; As[ak + 3][ar0] = pa0.w;
        As[ak + 0][ar1] = pa1.x; As[ak + 1][ar1] = pa1.y;
        As[ak + 2][ar1] = pa1.z; As[ak + 3][ar1] = pa1.w;
        Bs[bk + 0][br] = pb.x; Bs[bk + 1][br] = pb.y;
        Bs[bk + 2][br] = pb.z; Bs[bk + 3][br] = pb.w;
        __syncthreads();

        const int kn = k0 + BK;
        if (kn < H_DIM) {
            pa0 = *(const float4*)(Ap0 + kn);
            pa1 = *(const float4*)(Ap1 + kn);
            if (bvalid) pb = *(const float4*)(Wp + kn);
        }

#pragma unroll
        for (int k = 0; k < BK; k++) {
            float4 a0 = *(const float4*)(&As[k][ty * 8]);
            float4 a1 = *(const float4*)(&As[k][ty * 8 + 4]);
            float4 b4 = *(const float4*)(&Bs[k][tx * 4]);
            float av[8] = {a0.x, a0.y, a0.z, a0.w, a1.x, a1.y, a1.z, a1.w};
            float bv[4] = {b4.x, b4.y, b4.z, b4.w};
#pragma unroll
            for (int i = 0; i < 8; i++)
#pragma unroll
                for (int j = 0; j < 4; j++)
                    acc[i][j] = fmaf(av[i], bv[j], acc[i][j]);
        }
        __syncthreads();
    }

    const int c = col0 + tx * 4;
    if (c < OUT_DIM) {
        const float4 bb = *(const float4*)(bias + c);
#pragma unroll
        for (int i = 0; i < 8; i++) {
            const int r = row0 + ty * 8 + i;
            float4 o;
            o.x = acc[i][0] + bb.x; o.y = acc[i][1] + bb.y;
            o.z = acc[i][2] + bb.z; o.w = acc[i][3] + bb.w;
            *(float4*)(g_fc + (size_t)r * OUT_DIM + c) = o;
        }
    }
}

// ---------------- command: argmax(x/1e-4 + gumbel) over 4 -> one-hot ----------------
__global__ void command_kernel(float* __restrict__ out, uint32_t kc0, uint32_t kc1) {
    const int row = blockIdx.x * blockDim.x + threadIdx.x;
    if (row >= M_DIM) return;
    const float4 x4 = *(const float4*)(g_fc + (size_t)row * OUT_DIM);
    float x[4] = {x4.x, x4.y, x4.z, x4.w};

    int best = 0; float m = x[0];
#pragma unroll
    for (int c = 1; c < 4; c++) if (x[c] > m) { m = x[c]; best = c; }

    int nnear = 0;
#pragma unroll
    for (int c = 0; c < 4; c++) nnear += (x[c] > m - MARGIN) ? 1 : 0;

    if (nnear > 1) {
        float sb = NEG_BIG; int bi = 0;
#pragma unroll
        for (int c = 0; c < 4; c++) {
            if (x[c] > m - MARGIN) {
                float g = gumbel_u32(rand32(kc0, kc1, (uint32_t)(row * 4 + c)));
                float sc = g + __fdiv_rn(x[c], 1e-4f);
                if (sc > sb) { sb = sc; bi = c; }  // strict >: first index wins
            }
        }
        best = bi;
    }
    float2* o = (float2*)(out + (size_t)row * 10);
    o[0] = make_float2(best == 0 ? 1.f : 0.f, best == 1 ? 1.f : 0.f);
    o[1] = make_float2(best == 2 ? 1.f : 0.f, best == 3 ? 1.f : 0.f);
}

// ---------------- mixture + arguments: one warp per [50]-row ----------------
__global__ void mixture_kernel(float* __restrict__ out,
                               uint32_t km0, uint32_t km1,
                               uint32_t kg0, uint32_t kg1) {
    const int gwarp = (blockIdx.x * blockDim.x + threadIdx.x) >> 5;
    const int lane = threadIdx.x & 31;
    if (gwarp >= NARG) return;

    const int sb = gwarp / 6;
    const int j = gwarp - sb * 6;
    const float* base = g_fc + (size_t)sb * OUT_DIM + 4 + j * 150;

    const float x0 = base[lane];
    const float x1 = (lane < 18) ? base[32 + lane] : NEG_BIG;

    float m = fmaxf(x0, x1);
#pragma unroll
    for (int o = 16; o; o >>= 1) m = fmaxf(m, __shfl_xor_sync(0xffffffffu, m, o));

    const float th = m - MARGIN;
    const unsigned f0 = __ballot_sync(0xffffffffu, x0 > th);
    const unsigned f1 = __ballot_sync(0xffffffffu, x1 > th);

    int k;
    if (__popc(f0) + __popc(f1) == 1) {
        k = f0 ? (__ffs(f0) - 1) : (31 + __ffs(f1));
    } else {
        // slow path: exact logsumexp (sequential, index order) + gumbel scores
        int kk = 0;
        if (lane == 0) {
            float s = 0.0f;
            for (int i = 0; i < 50; i++) s += expf(base[i] - m);
            const float lse = logf(s) + m;
            float sbst = NEG_BIG;
            const uint32_t eb = (uint32_t)gwarp * 50u;
            for (int i = 0; i < 50; i++) {
                const float xi = base[i];
                if (xi > th) {
                    float g = gumbel_u32(rand32(km0, km1, eb + (uint32_t)i));
                    float sc = g + __fdiv_rn(xi - lse, 1e-4f);
                    if (sc > sbst) { sbst = sc; kk = i; }
                }
            }
        }
        k = __shfl_sync(0xffffffffu, kk, 0);
    }

    if (lane == 0) {
        const float mean = base[50 + k];
        const float lstd = base[100 + k];
        const float n = normal_u32(rand32(kg0, kg1, (uint32_t)gwarp));
        out[(size_t)sb * 10 + 4 + j] = mean + expf(lstd) * (n * 0.01f);
    }
}

// ---------------- host threefry for key derivation ----------------
static inline uint32_t h_rotl(uint32_t v, int r) { return (v << r) | (v >> (32 - r)); }
static void h_tf(uint32_t k0, uint32_t k1, uint32_t c0, uint32_t c1,
                 uint32_t* o0, uint32_t* o1) {
    uint32_t ks2 = k0 ^ k1 ^ 0x1BD11BDAu;
    uint32_t x0 = c0 + k0, x1 = c1 + k1;
    uint32_t ks[3] = {k0, k1, ks2};
    const int RA[4] = {13, 15, 26, 6};
    const int RB[4] = {17, 29, 16, 24};
    for (int blk = 0; blk < 5; blk++) {
        const int* rr = (blk & 1) ? RB : RA;
        for (int i = 0; i < 4; i++) {
            x0 += x1; x1 = h_rotl(x1, rr[i]); x1 ^= x0;
        }
        x0 += ks[(blk + 1) % 3];
        x1 += ks[(blk + 2) % 3] + (uint32_t)(blk + 1);
    }
    *o0 = x0; *o1 = x1;
}

extern "C" void kernel_launch(void* const* d_in, const int* in_sizes, int n_in,
                              void* d_out, int out_size) {
    const float* A = (const float*)d_in[0];   // decoder_output [51,2048,1024]
    const float* W = (const float*)d_in[1];   // [904,1024]
    const float* b = (const float*)d_in[2];   // [904]
    float* out = (float*)d_out;               // [51,2048,10]

    // split(key(42), 3) -> kc, km, kg  (partitionable: child i = tf(key,(0,i)))
    uint32_t kc0, kc1, km0, km1, kg0, kg1;
    h_tf(0u, 42u, 0u, 0u, &kc0, &kc1);
    h_tf(0u, 42u, 0u, 1u, &km0, &km1);
    h_tf(0u, 42u, 0u, 2u, &kg0, &kg1);

    dim3 ggrid((OUT_DIM + BN - 1) / BN, M_DIM / BM);
    gemm_kernel<<<ggrid, 256>>>(A, W, b);

    command_kernel<<<(M_DIM + 255) / 256, 256>>>(out, kc0, kc1);

    const int mwarps_per_block = 8;
    const int mblocks = (NARG + mwarps_per_block - 1) / mwarps_per_block;
    mixture_kernel<<<mblocks, mwarps_per_block * 32>>>(out, km0, km1, kg0, kg1);
}